// round 7
// baseline (speedup 1.0000x reference)
#include <cuda_runtime.h>
#include <cstdint>

// Problem sizes (fixed by the reference)
#define B_N 8
#define L_N 4096
#define F_N 64

#define TILE_M 256
#define KC 32                    // k floats per chunk
#define NCHUNK (L_N / KC)        // 128
#define STAGES 4                 // per-warp A stages

// Per-warp A stage: 32 rows x 32 floats = 4KB, XOR-swizzled 16B chunks
#define A_WSLOT 4096
#define SMEM_BYTES (8 * STAGES * A_WSLOT)   // 131072

// hidden, packed for LDG.128 B-fragment loads:
// float offset = ((b*512 + kb)*4 + j)*128 + group*16 + tig*4 + (nt&1)*2 + p
// where for element (b, l, o): kb=l>>3, kr=l&7, tig=kr&3, p=kr>>2,
//                              nt=o>>3, j=nt>>1, group=o&7
__device__ float g_hiddenP[(size_t)B_N * 512 * 512];

// ---------------------------------------------------------------------------
// helpers
// ---------------------------------------------------------------------------
__device__ __forceinline__ uint32_t smem_u32(const void* p) {
    uint32_t a;
    asm("{ .reg .u64 t; cvta.to.shared.u64 t, %1; cvt.u32.u64 %0, t; }" : "=r"(a) : "l"(p));
    return a;
}

__device__ __forceinline__ void cp16(uint32_t dst, const void* src) {
    asm volatile("cp.async.cg.shared.global [%0], [%1], 16;" :: "r"(dst), "l"(src) : "memory");
}

__device__ __forceinline__ void mma_tf32(float* c, uint32_t a0, uint32_t a1,
                                         uint32_t a2, uint32_t a3,
                                         uint32_t b0, uint32_t b1) {
    asm volatile(
        "mma.sync.aligned.m16n8k8.row.col.f32.tf32.tf32.f32 "
        "{%0,%1,%2,%3}, {%4,%5,%6,%7}, {%8,%9}, {%0,%1,%2,%3};"
        : "+f"(c[0]), "+f"(c[1]), "+f"(c[2]), "+f"(c[3])
        : "r"(a0), "r"(a1), "r"(a2), "r"(a3), "r"(b0), "r"(b1));
}

__device__ __forceinline__ float lds_f(const char* p) {
    return *reinterpret_cast<const float*>(p);
}

// ---------------------------------------------------------------------------
// Kernel A: hidden = text @ W, written tf32-rounded into LDG.128-packed layout
// ---------------------------------------------------------------------------
__global__ void __launch_bounds__(256) hidden_kernel(const float* __restrict__ text,
                                                     const float* __restrict__ weight) {
    __shared__ float s_text[64][65];
    __shared__ float s_w[64][64];
    const int b = blockIdx.y;
    const int l0 = blockIdx.x * 64;
    const int t = threadIdx.x;

    const float* tp = text + ((size_t)b * L_N + l0) * F_N;
#pragma unroll
    for (int j = 0; j < 16; j++) {
        int idx = j * 256 + t;  // 0..4095
        s_text[idx >> 6][idx & 63] = tp[idx];
        s_w[idx >> 6][idx & 63] = weight[idx];
    }
    __syncthreads();

    const int l = t & 63;
    const int og = t >> 6;  // 0..3 -> o = og*16 + i
    float acc[16];
#pragma unroll
    for (int i = 0; i < 16; i++) acc[i] = 0.0f;

    for (int f = 0; f < 64; f++) {
        float tv = s_text[l][f];
#pragma unroll
        for (int i = 0; i < 16; i++) acc[i] += tv * s_w[f][og * 16 + i];
    }

    const int lg = l0 + l;
    const int kb = lg >> 3;
    const int kr = lg & 7;
    const int tig = kr & 3;
    const int p = kr >> 2;
    float* dst = g_hiddenP + ((size_t)b * 512 + kb) * 512 + tig * 4 + p;
#pragma unroll
    for (int i = 0; i < 16; i++) {
        int o = og * 16 + i;
        int nt = o >> 3, j = nt >> 1, group = o & 7;
        uint32_t u;
        asm("cvt.rna.tf32.f32 %0, %1;" : "=r"(u) : "f"(acc[i]));
        dst[j * 128 + group * 16 + (nt & 1) * 2] = __uint_as_float(u);
    }
}

// ---------------------------------------------------------------------------
// Kernel B: out[b] = adj[b] @ hidden[b] + bias
// 256 threads (8 warps), 256x64 CTA tile, warp tile 32x64, mma.sync tf32.
// NO CTA barriers in the mainloop: per-warp A staging (cp.async + syncwarp),
// B fragments via coalesced LDG.128 (register double-buffered).
// ---------------------------------------------------------------------------
__global__ void __launch_bounds__(256, 1) gemm_kernel(const float* __restrict__ adj,
                                                      const float* __restrict__ bias,
                                                      float* __restrict__ out) {
    extern __shared__ char smem[];
    const uint32_t sb = smem_u32(smem);

    const int t = threadIdx.x;
    const int w = t >> 5;         // 0..7
    const int lane = t & 31;
    const int group = lane >> 2;  // 0..7
    const int tig = lane & 3;     // 0..3
    const int b = blockIdx.y;
    const int m0 = blockIdx.x * TILE_M;

    // warp's private A rows: m0 + w*32 .. +31
    const float* aG = adj + ((size_t)b * L_N + m0 + w * 32) * L_N;
    // B fragment base for this lane: + (kb*4 + j)*128 + ...
    const float* bF = g_hiddenP + (size_t)b * 512 * 512 + group * 16 + tig * 4;

    const uint32_t wbase = sb + w * (STAGES * A_WSLOT);
    char* wptr = smem + w * (STAGES * A_WSLOT);

    // ---- per-warp cp.async stage issue ----
    auto issueA = [&](int chunk, int slot) {
        uint32_t as = wbase + slot * A_WSLOT;
        const float* src = aG + chunk * KC;
#pragma unroll
        for (int jj = 0; jj < 8; jj++) {
            int q = jj * 32 + lane;      // 0..255
            int row = q >> 3, seg = q & 7;
            cp16(as + row * 128 + ((seg ^ (row & 7)) << 4),
                 src + (size_t)row * L_N + seg * 4);
        }
    };

    // B fragment load: chunk i, k8-step s -> 4 float4 (j=0..3)
#define LOADB(dst, chunk, s)                                                   \
    {                                                                          \
        const float* _p = bF + (((chunk) * 4 + (s)) * 4) * 128;                \
        (dst)[0] = __ldg(reinterpret_cast<const float4*>(_p));                 \
        (dst)[1] = __ldg(reinterpret_cast<const float4*>(_p + 128));           \
        (dst)[2] = __ldg(reinterpret_cast<const float4*>(_p + 256));           \
        (dst)[3] = __ldg(reinterpret_cast<const float4*>(_p + 384));           \
    }

    float acc[2][8][4];
#pragma unroll
    for (int mt = 0; mt < 2; mt++)
#pragma unroll
        for (int nt = 0; nt < 8; nt++)
#pragma unroll
            for (int r = 0; r < 4; r++) acc[mt][nt][r] = 0.0f;

    issueA(0, 0);
    asm volatile("cp.async.commit_group;" ::: "memory");
    issueA(1, 1);
    asm volatile("cp.async.commit_group;" ::: "memory");
    issueA(2, 2);
    asm volatile("cp.async.commit_group;" ::: "memory");

    float4 bq0[4], bq1[4];
    LOADB(bq0, 0, 0);

    for (int i = 0; i < NCHUNK; i++) {
        asm volatile("cp.async.wait_group 2;" ::: "memory");
        __syncwarp();

        const char* as = wptr + (i % STAGES) * A_WSLOT;
        const int nc = (i + 1 < NCHUNK) ? i + 1 : i;

#pragma unroll
        for (int s = 0; s < 4; s++) {
            // prefetch next s (or next chunk's s=0) into the other buffer
            if (s == 0) { LOADB(bq1, i, 1); }
            else if (s == 1) { LOADB(bq0, i, 2); }
            else if (s == 2) { LOADB(bq1, i, 3); }
            else { LOADB(bq0, nc, 0); }

            const float4* bq = (s & 1) ? bq1 : bq0;
            // use the buffer filled for step s: s0->bq0, s1->bq1, s2->bq0, s3->bq1
            const float4* cur = (s & 1) ? bq1 : bq0;
            (void)bq;

            // A fragments: swizzled 16B chunks
            const int c0 = ((2 * s) ^ group) << 4;
            const int c1 = ((2 * s + 1) ^ group) << 4;
#pragma unroll
            for (int mt = 0; mt < 2; mt++) {
                const int r0 = mt * 16 + group;   // local row
                const char* rp = as + r0 * 128;
                uint32_t a0 = __float_as_uint(lds_f(rp + c0 + tig * 4));
                uint32_t a2 = __float_as_uint(lds_f(rp + c1 + tig * 4));
                uint32_t a1 = __float_as_uint(lds_f(rp + 8 * 128 + c0 + tig * 4));
                uint32_t a3 = __float_as_uint(lds_f(rp + 8 * 128 + c1 + tig * 4));
#pragma unroll
                for (int jj = 0; jj < 4; jj++) {
                    mma_tf32(acc[mt][2 * jj], a0, a1, a2, a3,
                             __float_as_uint(cur[jj].x), __float_as_uint(cur[jj].y));
                    mma_tf32(acc[mt][2 * jj + 1], a0, a1, a2, a3,
                             __float_as_uint(cur[jj].z), __float_as_uint(cur[jj].w));
                }
            }
        }

        if (i + 3 < NCHUNK) issueA(i + 3, (i + 3) % STAGES);
        asm volatile("cp.async.commit_group;" ::: "memory");
    }

    // ---- epilogue: + bias, direct STG ----
#pragma unroll
    for (int mt = 0; mt < 2; mt++) {
        const int r0 = m0 + w * 32 + mt * 16 + group;
        float* op0 = out + ((size_t)b * L_N + r0) * F_N;
        float* op1 = op0 + 8 * F_N;
#pragma unroll
        for (int jj = 0; jj < 4; jj++) {
#pragma unroll
            for (int h = 0; h < 2; h++) {
                const int nt = 2 * jj + h;
                const int col = nt * 8 + tig * 2;
                const float b0 = __ldg(&bias[col]);
                const float b1 = __ldg(&bias[col + 1]);
                float2 v0 = make_float2(acc[mt][nt][0] + b0, acc[mt][nt][1] + b1);
                float2 v1 = make_float2(acc[mt][nt][2] + b0, acc[mt][nt][3] + b1);
                *reinterpret_cast<float2*>(op0 + col) = v0;
                *reinterpret_cast<float2*>(op1 + col) = v1;
            }
        }
    }
}

// ---------------------------------------------------------------------------
// launch
// ---------------------------------------------------------------------------
extern "C" void kernel_launch(void* const* d_in, const int* in_sizes, int n_in,
                              void* d_out, int out_size) {
    const float* text = (const float*)d_in[0];   // [8,4096,64]
    const float* adj = (const float*)d_in[1];    // [8,4096,4096]
    const float* weight = (const float*)d_in[2]; // [64,64]
    const float* bias = (const float*)d_in[3];   // [64]
    float* out = (float*)d_out;                  // [8,4096,64]

    cudaFuncSetAttribute(gemm_kernel, cudaFuncAttributeMaxDynamicSharedMemorySize,
                         SMEM_BYTES);

    hidden_kernel<<<dim3(L_N / 64, B_N), 256>>>(text, weight);
    gemm_kernel<<<dim3(L_N / TILE_M, B_N), 256, SMEM_BYTES>>>(adj, bias, out);
}